// round 16
// baseline (speedup 1.0000x reference)
#include <cuda_runtime.h>
#include <cuda_fp16.h>
#include <cuda_fp8.h>
#include <cstdint>
#include <math.h>

#define NN 50000
#define EE 600000
#define FF 128
#define HH 128
#define CC 16
#define GG 500
#define NB 196   // ceil(NN/256)

// ---------------- scratch (device globals; zero-initialized at load) ---------
__device__ int    g_indeg[NN];
__device__ int    g_cursor[NN];
__device__ int    g_offl[NN];        // block-local exclusive offsets
__device__ int    g_off[NN + 1];     // final offsets (written by k_csr)
__device__ float  g_dis[NN];
__device__ int    g_bsum[NB];
__device__ int    g_csri[EE];                   // src index only (norm factored out)
__device__ __align__(16) __half g_W1s[128 * 128];  // W1^T fp16, pre-swizzled
__device__ __align__(4) unsigned short g_h1f8[(size_t)NN * 64];  // dis[i]*(x@W1) fp8 e4m3
__device__ __half g_a1h[(size_t)NN * HH];       // relu(agg + b1) fp16
__device__ __half g_h2h[(size_t)NN * CC];       // dis[i] * (a1 @ W2) (fp16)
__device__ float  g_pool[GG * CC];
__device__ float  g_cnt[GG];

// ---------------- degree count + W1 convert (fused) + zero pool/cnt ------------
__global__ void k_deg(const int* __restrict__ dst, const float* __restrict__ W1) {
    int gid = blockIdx.x * blockDim.x + threadIdx.x;   // < EE/2
    if (gid < GG * CC) g_pool[gid] = 0.0f;
    if (gid < GG) g_cnt[gid] = 0.0f;
    if (gid < 128 * 128) {
        int k = gid >> 7;
        int n = gid & 127;
        int dstp = n * 128 + ((((k >> 3) ^ (n & 7)) << 3) | (k & 7));
        g_W1s[dstp] = __float2half_rn(W1[gid]);
    }
    if (gid < EE / 2) {
        int2 d2 = ((const int2*)dst)[gid];
        atomicAdd(&g_indeg[d2.x], 1);
        atomicAdd(&g_indeg[d2.y], 1);
    }
}

// ---------------- scan phase 1: per-block scan + dis ---------------------------
__global__ __launch_bounds__(256) void k_part() {
    const int t = threadIdx.x;
    const int i = blockIdx.x * 256 + t;
    int v = (i < NN) ? g_indeg[i] : 0;
    if (i < NN) g_dis[i] = rsqrtf((float)v + 1.0f);   // +1 = self loop

    const int lane = t & 31, w = t >> 5;
    int x = v;
#pragma unroll
    for (int d = 1; d < 32; d <<= 1) {
        int y = __shfl_up_sync(0xffffffffu, x, d);
        if (lane >= d) x += y;
    }
    __shared__ int wsum[8];
    if (lane == 31) wsum[w] = x;
    __syncthreads();
    if (t < 8) {
        int y = wsum[t];
#pragma unroll
        for (int d = 1; d < 8; d <<= 1) {
            int z = __shfl_up_sync(0xffu, y, d);
            if (t >= d) y += z;
        }
        wsum[t] = y;
    }
    __syncthreads();
    int incl = x + ((w > 0) ? wsum[w - 1] : 0);
    if (i < NN) g_offl[i] = incl - v;       // local exclusive
    if (t == 255) g_bsum[blockIdx.x] = incl;
}

// ---------------- CSR fill (src only) + offset finalization --------------------
__global__ __launch_bounds__(256) void k_csr(const int* __restrict__ src,
                                             const int* __restrict__ dst) {
    const int t   = threadIdx.x;
    const int bid = blockIdx.x;
    const int lane = t & 31, w = t >> 5;

    __shared__ int sbase[256];
    __shared__ int wsum[8];
    int v = (t < NB) ? g_bsum[t] : 0;
    int x = v;
#pragma unroll
    for (int d = 1; d < 32; d <<= 1) {
        int y = __shfl_up_sync(0xffffffffu, x, d);
        if (lane >= d) x += y;
    }
    if (lane == 31) wsum[w] = x;
    __syncthreads();
    if (t < 8) {
        int y = wsum[t];
#pragma unroll
        for (int d = 1; d < 8; d <<= 1) {
            int z = __shfl_up_sync(0xffu, y, d);
            if (t >= d) y += z;
        }
        wsum[t] = y;
    }
    __syncthreads();
    sbase[t] = (x + ((w > 0) ? wsum[w - 1] : 0)) - v;   // exclusive
    __syncthreads();

    const int gid = bid * 256 + t;           // < EE/2
    if (gid < EE / 2) {
        int2 s2 = ((const int2*)src)[gid];
        int2 d2 = ((const int2*)dst)[gid];
        {
            int off_d = g_offl[d2.x] + sbase[d2.x >> 8];
            int p = off_d + atomicAdd(&g_cursor[d2.x], 1);
            g_csri[p] = s2.x;
        }
        {
            int off_d = g_offl[d2.y] + sbase[d2.y >> 8];
            int p = off_d + atomicAdd(&g_cursor[d2.y], 1);
            g_csri[p] = s2.y;
        }
    }
    if (bid < NB) {
        int i = bid * 256 + t;
        if (i < NN) g_off[i] = g_offl[i] + sbase[bid];
    }
    if (bid == 0 && t == 0) g_off[NN] = EE;
}

// ---------------- GEMM1: h1s = fp8( dis[i]*(x @ W1) ), single-K, swizzled ------
__global__ __launch_bounds__(256) void k_gemm1(const float* __restrict__ x) {
    __shared__ __align__(16) __half As[64 * 128];
    __shared__ __align__(16) __half Bs[128 * 128];
    const int tid  = threadIdx.x;
    const int wid  = tid >> 5;
    const int lane = tid & 31;
    const int g    = lane >> 2;
    const int q    = lane & 3;
    const int m0   = blockIdx.x * 64;
    const int mw   = (wid & 3) * 16;       // warp m-slice within tile
    const int nb   = (wid >> 2) * 64;      // warp n-half base

    // load x tile: 8 independent float4 LDGs, convert+scale, store swizzled
    float4 v[8];
    float  dv[8];
#pragma unroll
    for (int it = 0; it < 8; it++) {
        int idx = it * 256 + tid;
        int r   = idx >> 5;                // row 0..63
        int c4  = idx & 31;
        int row = m0 + r;
        if (row < NN) {
            v[it]  = ((const float4*)(x + (size_t)row * 128))[c4];
            dv[it] = g_dis[row];
        } else {
            v[it]  = make_float4(0.f, 0.f, 0.f, 0.f);
            dv[it] = 0.0f;
        }
    }
#pragma unroll
    for (int it = 0; it < 8; it++) {
        int idx = it * 256 + tid;
        int r   = idx >> 5;
        int c4  = idx & 31;
        __half2 h0 = __floats2half2_rn(v[it].x * dv[it], v[it].y * dv[it]);
        __half2 h1 = __floats2half2_rn(v[it].z * dv[it], v[it].w * dv[it]);
        int cc = (c4 >> 1) ^ (r & 7);      // 16B chunk swizzle
        char* p = (char*)As + r * 256 + cc * 16 + (c4 & 1) * 8;
        ((unsigned int*)p)[0] = *(unsigned int*)&h0;
        ((unsigned int*)p)[1] = *(unsigned int*)&h1;
    }
    // bulk-copy pre-swizzled W1^T (2048 uint4, 8 per thread)
    {
        const uint4* srcB = (const uint4*)g_W1s;
        uint4* dstB = (uint4*)Bs;
#pragma unroll
        for (int it = 0; it < 8; it++) dstB[it * 256 + tid] = srcB[it * 256 + tid];
    }
    __syncthreads();

    float acc[8][4];
#pragma unroll
    for (int n = 0; n < 8; n++)
#pragma unroll
        for (int c = 0; c < 4; c++) acc[n][c] = 0.0f;

    const char* ar0 = (const char*)As + (mw + g) * 256;
    const char* ar1 = (const char*)As + (mw + g + 8) * 256;
#pragma unroll
    for (int ks = 0; ks < 8; ks++) {
        const int o0 = (((2 * ks)     ^ g) << 4) + 4 * q;
        const int o1 = (((2 * ks + 1) ^ g) << 4) + 4 * q;
        unsigned int a0 = *(const unsigned int*)(ar0 + o0);
        unsigned int a1 = *(const unsigned int*)(ar1 + o0);
        unsigned int a2 = *(const unsigned int*)(ar0 + o1);
        unsigned int a3 = *(const unsigned int*)(ar1 + o1);
#pragma unroll
        for (int nt = 0; nt < 8; nt++) {
            const char* br = (const char*)Bs + (nb + nt * 8 + g) * 256;
            unsigned int b0 = *(const unsigned int*)(br + o0);
            unsigned int b1 = *(const unsigned int*)(br + o1);
            asm volatile(
                "mma.sync.aligned.m16n8k16.row.col.f32.f16.f16.f32 "
                "{%0,%1,%2,%3}, {%4,%5,%6,%7}, {%8,%9}, {%0,%1,%2,%3};"
                : "+f"(acc[nt][0]), "+f"(acc[nt][1]),
                  "+f"(acc[nt][2]), "+f"(acc[nt][3])
                : "r"(a0), "r"(a1), "r"(a2), "r"(a3), "r"(b0), "r"(b1));
        }
    }

    // epilogue: fp8 e4m3 store (2 cols = 1 ushort)
    const int r0 = m0 + mw + g;
#pragma unroll
    for (int nt = 0; nt < 8; nt++) {
        int n = nb + nt * 8 + q * 2;
        if (r0 < NN) {
            __nv_fp8x2_storage_t p0 = __nv_cvt_float2_to_fp8x2(
                make_float2(acc[nt][0], acc[nt][1]), __NV_SATFINITE, __NV_E4M3);
            g_h1f8[(size_t)r0 * 64 + (n >> 1)] = (unsigned short)p0;
        }
        if (r0 + 8 < NN) {
            __nv_fp8x2_storage_t p1 = __nv_cvt_float2_to_fp8x2(
                make_float2(acc[nt][2], acc[nt][3]), __NV_SATFINITE, __NV_E4M3);
            g_h1f8[(size_t)(r0 + 8) * 64 + (n >> 1)] = (unsigned short)p1;
        }
    }
}

// ---------------- agg1: a1 = relu( dis[i]*(h1s[i] + sum h1s[src]) + b1 ) --------
__device__ __forceinline__ float4 f8x4_to_f4(unsigned int u) {
    __half2_raw lo = __nv_cvt_fp8x2_to_halfraw2(
        (__nv_fp8x2_storage_t)(u & 0xffffu), __NV_E4M3);
    __half2_raw hi = __nv_cvt_fp8x2_to_halfraw2(
        (__nv_fp8x2_storage_t)(u >> 16), __NV_E4M3);
    float2 a = __half22float2(*(__half2*)&lo);
    float2 b = __half22float2(*(__half2*)&hi);
    return make_float4(a.x, a.y, b.x, b.y);
}

__global__ __launch_bounds__(256) void k_agg1(const float* __restrict__ b1) {
    const int gw   = (blockIdx.x * 256 + threadIdx.x) >> 5;   // node
    const int lane = threadIdx.x & 31;                         // 4-feat chunk
    {
        int gt = blockIdx.x * 256 + threadIdx.x;
        if (gt < NN) { g_indeg[gt] = 0; g_cursor[gt] = 0; }
    }
    if (gw >= NN) return;
    const unsigned int* __restrict__ h1 = (const unsigned int*)g_h1f8;

    float4 acc = f8x4_to_f4(h1[(size_t)gw * 32 + lane]);   // self (pre-scaled)

    int j = g_off[gw];
    const int e = g_off[gw + 1];
    for (; j + 3 < e; j += 4) {
        int s0 = g_csri[j];
        int s1 = g_csri[j + 1];
        int s2 = g_csri[j + 2];
        int s3 = g_csri[j + 3];
        unsigned int r0 = h1[(size_t)s0 * 32 + lane];
        unsigned int r1 = h1[(size_t)s1 * 32 + lane];
        unsigned int r2 = h1[(size_t)s2 * 32 + lane];
        unsigned int r3 = h1[(size_t)s3 * 32 + lane];
        float4 hA = f8x4_to_f4(r0), hB = f8x4_to_f4(r1);
        float4 hC = f8x4_to_f4(r2), hD = f8x4_to_f4(r3);
        acc.x += hA.x + hB.x + hC.x + hD.x;
        acc.y += hA.y + hB.y + hC.y + hD.y;
        acc.z += hA.z + hB.z + hC.z + hD.z;
        acc.w += hA.w + hB.w + hC.w + hD.w;
    }
    for (; j < e; j++) {
        float4 hA = f8x4_to_f4(h1[(size_t)g_csri[j] * 32 + lane]);
        acc.x += hA.x; acc.y += hA.y; acc.z += hA.z; acc.w += hA.w;
    }
    const float di = g_dis[gw];
    float4 bb = ((const float4*)b1)[lane];
    __half2 p0 = __floats2half2_rn(fmaxf(fmaf(acc.x, di, bb.x), 0.0f),
                                   fmaxf(fmaf(acc.y, di, bb.y), 0.0f));
    __half2 p1 = __floats2half2_rn(fmaxf(fmaf(acc.z, di, bb.z), 0.0f),
                                   fmaxf(fmaf(acc.w, di, bb.w), 0.0f));
    uint2 st;
    st.x = *(unsigned int*)&p0;
    st.y = *(unsigned int*)&p1;
    ((uint2*)g_a1h)[(size_t)gw * 32 + lane] = st;
}

// ---------------- GEMM2: h2s(fp16) = dis[i] * (a1 @ W2) -------------------------
__global__ __launch_bounds__(256) void k_gemm2(const float* __restrict__ W2) {
    __shared__ float WsT[16][132];
    const int tid = threadIdx.x;
#pragma unroll
    for (int it = 0; it < 8; it++) {
        int idx = tid + it * 256;
        int k = idx >> 4, c = idx & 15;
        WsT[c][k] = W2[idx];
    }
    __syncthreads();

    int gid = blockIdx.x * 256 + tid;   // exact: 50000*16/256 = 3125 blocks
    int i = gid >> 4;
    int c = gid & 15;
    const uint4* __restrict__ row = (const uint4*)(g_a1h + (size_t)i * 128);
    const float* wt = WsT[c];
    float acc = 0.0f;
#pragma unroll
    for (int k8 = 0; k8 < 16; k8++) {
        uint4 u = row[k8];
        float2 f0 = __half22float2(*(__half2*)&u.x);
        float2 f1 = __half22float2(*(__half2*)&u.y);
        float2 f2 = __half22float2(*(__half2*)&u.z);
        float2 f3 = __half22float2(*(__half2*)&u.w);
        const float* wk = wt + k8 * 8;
        acc = fmaf(f0.x, wk[0], acc); acc = fmaf(f0.y, wk[1], acc);
        acc = fmaf(f1.x, wk[2], acc); acc = fmaf(f1.y, wk[3], acc);
        acc = fmaf(f2.x, wk[4], acc); acc = fmaf(f2.y, wk[5], acc);
        acc = fmaf(f3.x, wk[6], acc); acc = fmaf(f3.y, wk[7], acc);
    }
    g_h2h[(size_t)i * 16 + c] = __float2half_rn(acc * g_dis[i]);
}

// ---------------- agg2: pool += dis[i]*(h2s[i] + sum h2s[src]) + b2 -------------
__global__ __launch_bounds__(128) void k_agg2_pool(const float* __restrict__ b2,
                                                   const int* __restrict__ batch) {
    const int tid  = threadIdx.x;
    const int lane = tid & 15;
    const int i    = blockIdx.x * 8 + (tid >> 4);
    if (i >= NN) return;
    float acc = __half2float(g_h2h[(size_t)i * 16 + lane]);   // self (pre-scaled)
    int j = g_off[i];
    const int s1 = g_off[i + 1];
    for (; j + 3 < s1; j += 4) {
        int c0 = g_csri[j];
        int c1 = g_csri[j + 1];
        int c2 = g_csri[j + 2];
        int c3 = g_csri[j + 3];
        float hA = __half2float(g_h2h[(size_t)c0 * 16 + lane]);
        float hB = __half2float(g_h2h[(size_t)c1 * 16 + lane]);
        float hC = __half2float(g_h2h[(size_t)c2 * 16 + lane]);
        float hD = __half2float(g_h2h[(size_t)c3 * 16 + lane]);
        acc += hA + hB + hC + hD;
    }
    for (; j < s1; j++)
        acc += __half2float(g_h2h[(size_t)g_csri[j] * 16 + lane]);
    acc = fmaf(acc, g_dis[i], b2[lane]);
    int b = batch[i];
    atomicAdd(&g_pool[b * 16 + lane], acc);
    if (lane == 0) atomicAdd(&g_cnt[b], 1.0f);
}

// ---------------- mean + log_softmax ---------------------------------------------
__global__ __launch_bounds__(256) void k_out(float* __restrict__ out) {
    const int tid = threadIdx.x;
    const int c = tid & 15;
    const int r = blockIdx.x * 16 + (tid >> 4);
    float v = 0.0f;
    if (r < GG) v = g_pool[r * 16 + c] / fmaxf(g_cnt[r], 1.0f);
    float m = v;
#pragma unroll
    for (int k = 8; k; k >>= 1) m = fmaxf(m, __shfl_xor_sync(0xffffffffu, m, k, 16));
    float e = expf(v - m);
    float s = e;
#pragma unroll
    for (int k = 8; k; k >>= 1) s += __shfl_xor_sync(0xffffffffu, s, k, 16);
    if (r < GG) out[r * 16 + c] = v - m - logf(s);
}

// -----------------------------------------------------------------------------------
extern "C" void kernel_launch(void* const* d_in, const int* in_sizes, int n_in,
                              void* d_out, int out_size) {
    const float* x   = (const float*)d_in[0];
    const float* W1  = (const float*)d_in[1];
    const float* b1  = (const float*)d_in[2];
    const float* W2  = (const float*)d_in[3];
    const float* b2  = (const float*)d_in[4];
    const int* esrc  = (const int*)d_in[5];
    const int* edst  = (const int*)d_in[6];
    const int* batch = (const int*)d_in[7];
    float* out = (float*)d_out;

    // one side stream + two events (proven resource envelope)
    cudaStream_t side;
    cudaEvent_t evP, evB;
    cudaStreamCreateWithFlags(&side, cudaStreamNonBlocking);
    cudaEventCreateWithFlags(&evP, cudaEventDisableTiming);
    cudaEventCreateWithFlags(&evB, cudaEventDisableTiming);

    k_deg<<<(EE / 2 + 255) / 256, 256>>>(edst, W1);        // #1 (main, + W1 cvt)
    k_part<<<NB, 256>>>();                                 // #2 (main)
    cudaEventRecord(evP, 0);                               // dis + W1s ready
    cudaStreamWaitEvent(side, evP, 0);
    k_gemm1<<<(NN + 63) / 64, 256, 0, side>>>(x);          // #3 (side)
    cudaEventRecord(evB, side);

    k_csr<<<(EE / 2 + 255) / 256, 256>>>(esrc, edst);      // #4 (main) <- ncu

    cudaStreamWaitEvent(0, evB, 0);
    k_agg1<<<(NN * 32 + 255) / 256, 256>>>(b1);            // #5
    k_gemm2<<<(NN * CC) / 256, 256>>>(W2);                 // #6
    k_agg2_pool<<<(NN + 7) / 8, 128>>>(b2, batch);         // #7
    k_out<<<(GG + 15) / 16, 256>>>(out);                   // #8
}

// round 17
// speedup vs baseline: 1.0257x; 1.0257x over previous
#include <cuda_runtime.h>
#include <cuda_fp16.h>
#include <cstdint>
#include <math.h>

#define NN 50000
#define EE 600000
#define FF 128
#define HH 128
#define CC 16
#define GG 500
#define NB 196   // ceil(NN/256)

// ---------------- scratch (device globals; zero-initialized at load) ---------
__device__ int    g_indeg[NN];
__device__ int    g_cursor[NN];      // pre-seeded with offl by k_part
__device__ int    g_offl[NN];        // block-local exclusive offsets
__device__ int    g_off[NN + 1];     // final offsets (written by k_csr)
__device__ float  g_dis[NN];
__device__ int    g_bsum[NB];
__device__ int    g_csri[EE];                   // src index only (norm factored out)
__device__ __align__(16) __half g_W1s[128 * 128];  // W1^T fp16, pre-swizzled
__device__ __half g_h1h[(size_t)NN * HH];       // dis[i] * (x @ W1)  (fp16)
__device__ __half g_a1h[(size_t)NN * HH];       // relu(agg + b1) fp16
__device__ __half g_h2h[(size_t)NN * CC];       // dis[i] * (a1 @ W2) (fp16)
__device__ float  g_pool[GG * CC];
__device__ float  g_cnt[GG];

// ---------------- degree count + W1 convert (fused) + zero pool/cnt ------------
__global__ void k_deg(const int* __restrict__ dst, const float* __restrict__ W1) {
    int gid = blockIdx.x * blockDim.x + threadIdx.x;   // < EE/2
    if (gid < GG * CC) g_pool[gid] = 0.0f;
    if (gid < GG) g_cnt[gid] = 0.0f;
    if (gid < 128 * 128) {
        int k = gid >> 7;
        int n = gid & 127;
        int dstp = n * 128 + ((((k >> 3) ^ (n & 7)) << 3) | (k & 7));
        g_W1s[dstp] = __float2half_rn(W1[gid]);
    }
    if (gid < EE / 2) {
        int2 d2 = ((const int2*)dst)[gid];
        atomicAdd(&g_indeg[d2.x], 1);
        atomicAdd(&g_indeg[d2.y], 1);
    }
}

// ---------------- scan phase 1: per-block scan + dis + cursor seed -------------
__global__ __launch_bounds__(256) void k_part() {
    const int t = threadIdx.x;
    const int i = blockIdx.x * 256 + t;
    int v = (i < NN) ? g_indeg[i] : 0;
    if (i < NN) g_dis[i] = rsqrtf((float)v + 1.0f);   // +1 = self loop

    const int lane = t & 31, w = t >> 5;
    int x = v;
#pragma unroll
    for (int d = 1; d < 32; d <<= 1) {
        int y = __shfl_up_sync(0xffffffffu, x, d);
        if (lane >= d) x += y;
    }
    __shared__ int wsum[8];
    if (lane == 31) wsum[w] = x;
    __syncthreads();
    if (t < 8) {
        int y = wsum[t];
#pragma unroll
        for (int d = 1; d < 8; d <<= 1) {
            int z = __shfl_up_sync(0xffu, y, d);
            if (t >= d) y += z;
        }
        wsum[t] = y;
    }
    __syncthreads();
    int incl = x + ((w > 0) ? wsum[w - 1] : 0);
    if (i < NN) {
        int offl = incl - v;
        g_offl[i]   = offl;       // local exclusive
        g_cursor[i] = offl;       // seed: atomicAdd returns offl-based slot
    }
    if (t == 255) g_bsum[blockIdx.x] = incl;
}

// ---------------- CSR fill: atomic carries base; no random offl load -----------
__global__ __launch_bounds__(256) void k_csr(const int* __restrict__ src,
                                             const int* __restrict__ dst) {
    const int t   = threadIdx.x;
    const int bid = blockIdx.x;
    const int lane = t & 31, w = t >> 5;

    __shared__ int sbase[256];
    __shared__ int wsum[8];
    int v = (t < NB) ? g_bsum[t] : 0;
    int x = v;
#pragma unroll
    for (int d = 1; d < 32; d <<= 1) {
        int y = __shfl_up_sync(0xffffffffu, x, d);
        if (lane >= d) x += y;
    }
    if (lane == 31) wsum[w] = x;
    __syncthreads();
    if (t < 8) {
        int y = wsum[t];
#pragma unroll
        for (int d = 1; d < 8; d <<= 1) {
            int z = __shfl_up_sync(0xffu, y, d);
            if (t >= d) y += z;
        }
        wsum[t] = y;
    }
    __syncthreads();
    sbase[t] = (x + ((w > 0) ? wsum[w - 1] : 0)) - v;   // exclusive
    __syncthreads();

    const int gid = bid * 256 + t;           // < EE/2
    if (gid < EE / 2) {
        int2 s2 = ((const int2*)src)[gid];
        int2 d2 = ((const int2*)dst)[gid];
        {
            int p = atomicAdd(&g_cursor[d2.x], 1) + sbase[d2.x >> 8];
            g_csri[p] = s2.x;
        }
        {
            int p = atomicAdd(&g_cursor[d2.y], 1) + sbase[d2.y >> 8];
            g_csri[p] = s2.y;
        }
    }
    if (bid < NB) {
        int i = bid * 256 + t;
        if (i < NN) g_off[i] = g_offl[i] + sbase[bid];
    }
    if (bid == 0 && t == 0) g_off[NN] = EE;
}

// ---------------- GEMM1: h1s = fp16( dis[i]*(x @ W1) ), single-K, swizzled -----
__global__ __launch_bounds__(256) void k_gemm1(const float* __restrict__ x) {
    __shared__ __align__(16) __half As[64 * 128];
    __shared__ __align__(16) __half Bs[128 * 128];
    const int tid  = threadIdx.x;
    const int wid  = tid >> 5;
    const int lane = tid & 31;
    const int g    = lane >> 2;
    const int q    = lane & 3;
    const int m0   = blockIdx.x * 64;
    const int mw   = (wid & 3) * 16;
    const int nb   = (wid >> 2) * 64;

    float4 v[8];
    float  dv[8];
#pragma unroll
    for (int it = 0; it < 8; it++) {
        int idx = it * 256 + tid;
        int r   = idx >> 5;
        int c4  = idx & 31;
        int row = m0 + r;
        if (row < NN) {
            v[it]  = ((const float4*)(x + (size_t)row * 128))[c4];
            dv[it] = g_dis[row];
        } else {
            v[it]  = make_float4(0.f, 0.f, 0.f, 0.f);
            dv[it] = 0.0f;
        }
    }
#pragma unroll
    for (int it = 0; it < 8; it++) {
        int idx = it * 256 + tid;
        int r   = idx >> 5;
        int c4  = idx & 31;
        __half2 h0 = __floats2half2_rn(v[it].x * dv[it], v[it].y * dv[it]);
        __half2 h1 = __floats2half2_rn(v[it].z * dv[it], v[it].w * dv[it]);
        int cc = (c4 >> 1) ^ (r & 7);
        char* p = (char*)As + r * 256 + cc * 16 + (c4 & 1) * 8;
        ((unsigned int*)p)[0] = *(unsigned int*)&h0;
        ((unsigned int*)p)[1] = *(unsigned int*)&h1;
    }
    {
        const uint4* srcB = (const uint4*)g_W1s;
        uint4* dstB = (uint4*)Bs;
#pragma unroll
        for (int it = 0; it < 8; it++) dstB[it * 256 + tid] = srcB[it * 256 + tid];
    }
    __syncthreads();

    float acc[8][4];
#pragma unroll
    for (int n = 0; n < 8; n++)
#pragma unroll
        for (int c = 0; c < 4; c++) acc[n][c] = 0.0f;

    const char* ar0 = (const char*)As + (mw + g) * 256;
    const char* ar1 = (const char*)As + (mw + g + 8) * 256;
#pragma unroll
    for (int ks = 0; ks < 8; ks++) {
        const int o0 = (((2 * ks)     ^ g) << 4) + 4 * q;
        const int o1 = (((2 * ks + 1) ^ g) << 4) + 4 * q;
        unsigned int a0 = *(const unsigned int*)(ar0 + o0);
        unsigned int a1 = *(const unsigned int*)(ar1 + o0);
        unsigned int a2 = *(const unsigned int*)(ar0 + o1);
        unsigned int a3 = *(const unsigned int*)(ar1 + o1);
#pragma unroll
        for (int nt = 0; nt < 8; nt++) {
            const char* br = (const char*)Bs + (nb + nt * 8 + g) * 256;
            unsigned int b0 = *(const unsigned int*)(br + o0);
            unsigned int b1 = *(const unsigned int*)(br + o1);
            asm volatile(
                "mma.sync.aligned.m16n8k16.row.col.f32.f16.f16.f32 "
                "{%0,%1,%2,%3}, {%4,%5,%6,%7}, {%8,%9}, {%0,%1,%2,%3};"
                : "+f"(acc[nt][0]), "+f"(acc[nt][1]),
                  "+f"(acc[nt][2]), "+f"(acc[nt][3])
                : "r"(a0), "r"(a1), "r"(a2), "r"(a3), "r"(b0), "r"(b1));
        }
    }

    const int r0 = m0 + mw + g;
#pragma unroll
    for (int nt = 0; nt < 8; nt++) {
        int n = nb + nt * 8 + q * 2;
        if (r0 < NN)
            *(__half2*)&g_h1h[(size_t)r0 * 128 + n] = __floats2half2_rn(acc[nt][0], acc[nt][1]);
        if (r0 + 8 < NN)
            *(__half2*)&g_h1h[(size_t)(r0 + 8) * 128 + n] = __floats2half2_rn(acc[nt][2], acc[nt][3]);
    }
}

// ---------------- agg1: 2 nodes/warp (16 lanes x 8 feats), fp16 gathers --------
__device__ __forceinline__ void u4_acc(float* a, uint4 u) {
    float2 f0 = __half22float2(*(__half2*)&u.x);
    float2 f1 = __half22float2(*(__half2*)&u.y);
    float2 f2 = __half22float2(*(__half2*)&u.z);
    float2 f3 = __half22float2(*(__half2*)&u.w);
    a[0] += f0.x; a[1] += f0.y; a[2] += f1.x; a[3] += f1.y;
    a[4] += f2.x; a[5] += f2.y; a[6] += f3.x; a[7] += f3.y;
}

__global__ __launch_bounds__(256) void k_agg1(const float* __restrict__ b1) {
    const int tid  = threadIdx.x;
    const int gw   = (blockIdx.x * 256 + tid) >> 5;     // warp id
    const int lane = tid & 31;
    const int half = lane >> 4;                          // 0/1 -> node select
    const int l16  = lane & 15;                          // uint4 chunk (8 feats)
    {
        int gt = blockIdx.x * 256 + tid;                 // 3125*256 = 800000 >= NN
        if (gt < NN) g_indeg[gt] = 0;                    // reset for next run
    }
    const int node = gw * 2 + half;
    if (node >= NN) return;
    const uint4* __restrict__ h1 = (const uint4*)g_h1h;  // row stride = 16 uint4

    float acc[8] = {0, 0, 0, 0, 0, 0, 0, 0};
    u4_acc(acc, h1[(size_t)node * 16 + l16]);            // self (pre-scaled)

    int j = g_off[node];
    const int e = g_off[node + 1];
    for (; j + 3 < e; j += 4) {
        int s0 = g_csri[j];
        int s1 = g_csri[j + 1];
        int s2 = g_csri[j + 2];
        int s3 = g_csri[j + 3];
        uint4 r0 = h1[(size_t)s0 * 16 + l16];
        uint4 r1 = h1[(size_t)s1 * 16 + l16];
        uint4 r2 = h1[(size_t)s2 * 16 + l16];
        uint4 r3 = h1[(size_t)s3 * 16 + l16];
        u4_acc(acc, r0); u4_acc(acc, r1); u4_acc(acc, r2); u4_acc(acc, r3);
    }
    for (; j < e; j++)
        u4_acc(acc, h1[(size_t)g_csri[j] * 16 + l16]);

    const float di = g_dis[node];
    float4 bb0 = ((const float4*)b1)[l16 * 2];
    float4 bb1 = ((const float4*)b1)[l16 * 2 + 1];
    __half2 p0 = __floats2half2_rn(fmaxf(fmaf(acc[0], di, bb0.x), 0.0f),
                                   fmaxf(fmaf(acc[1], di, bb0.y), 0.0f));
    __half2 p1 = __floats2half2_rn(fmaxf(fmaf(acc[2], di, bb0.z), 0.0f),
                                   fmaxf(fmaf(acc[3], di, bb0.w), 0.0f));
    __half2 p2 = __floats2half2_rn(fmaxf(fmaf(acc[4], di, bb1.x), 0.0f),
                                   fmaxf(fmaf(acc[5], di, bb1.y), 0.0f));
    __half2 p3 = __floats2half2_rn(fmaxf(fmaf(acc[6], di, bb1.z), 0.0f),
                                   fmaxf(fmaf(acc[7], di, bb1.w), 0.0f));
    uint4 st;
    st.x = *(unsigned int*)&p0;
    st.y = *(unsigned int*)&p1;
    st.z = *(unsigned int*)&p2;
    st.w = *(unsigned int*)&p3;
    ((uint4*)g_a1h)[(size_t)node * 16 + l16] = st;
}

// ---------------- GEMM2: h2s(fp16) = dis[i] * (a1 @ W2) -------------------------
__global__ __launch_bounds__(256) void k_gemm2(const float* __restrict__ W2) {
    __shared__ float WsT[16][132];
    const int tid = threadIdx.x;
#pragma unroll
    for (int it = 0; it < 8; it++) {
        int idx = tid + it * 256;
        int k = idx >> 4, c = idx & 15;
        WsT[c][k] = W2[idx];
    }
    __syncthreads();

    int gid = blockIdx.x * 256 + tid;   // exact: 50000*16/256 = 3125 blocks
    int i = gid >> 4;
    int c = gid & 15;
    const uint4* __restrict__ row = (const uint4*)(g_a1h + (size_t)i * 128);
    const float* wt = WsT[c];
    float acc = 0.0f;
#pragma unroll
    for (int k8 = 0; k8 < 16; k8++) {
        uint4 u = row[k8];
        float2 f0 = __half22float2(*(__half2*)&u.x);
        float2 f1 = __half22float2(*(__half2*)&u.y);
        float2 f2 = __half22float2(*(__half2*)&u.z);
        float2 f3 = __half22float2(*(__half2*)&u.w);
        const float* wk = wt + k8 * 8;
        acc = fmaf(f0.x, wk[0], acc); acc = fmaf(f0.y, wk[1], acc);
        acc = fmaf(f1.x, wk[2], acc); acc = fmaf(f1.y, wk[3], acc);
        acc = fmaf(f2.x, wk[4], acc); acc = fmaf(f2.y, wk[5], acc);
        acc = fmaf(f3.x, wk[6], acc); acc = fmaf(f3.y, wk[7], acc);
    }
    g_h2h[(size_t)i * 16 + c] = __float2half_rn(acc * g_dis[i]);
}

// ---------------- agg2: pool += dis[i]*(h2s[i] + sum h2s[src]) + b2 -------------
__global__ __launch_bounds__(128) void k_agg2_pool(const float* __restrict__ b2,
                                                   const int* __restrict__ batch) {
    const int tid  = threadIdx.x;
    const int lane = tid & 15;
    const int i    = blockIdx.x * 8 + (tid >> 4);
    if (i >= NN) return;
    float acc = __half2float(g_h2h[(size_t)i * 16 + lane]);   // self (pre-scaled)
    int j = g_off[i];
    const int s1 = g_off[i + 1];
    for (; j + 3 < s1; j += 4) {
        int c0 = g_csri[j];
        int c1 = g_csri[j + 1];
        int c2 = g_csri[j + 2];
        int c3 = g_csri[j + 3];
        float hA = __half2float(g_h2h[(size_t)c0 * 16 + lane]);
        float hB = __half2float(g_h2h[(size_t)c1 * 16 + lane]);
        float hC = __half2float(g_h2h[(size_t)c2 * 16 + lane]);
        float hD = __half2float(g_h2h[(size_t)c3 * 16 + lane]);
        acc += hA + hB + hC + hD;
    }
    for (; j < s1; j++)
        acc += __half2float(g_h2h[(size_t)g_csri[j] * 16 + lane]);
    acc = fmaf(acc, g_dis[i], b2[lane]);
    int b = batch[i];
    atomicAdd(&g_pool[b * 16 + lane], acc);
    if (lane == 0) atomicAdd(&g_cnt[b], 1.0f);
}

// ---------------- mean + log_softmax ---------------------------------------------
__global__ __launch_bounds__(256) void k_out(float* __restrict__ out) {
    const int tid = threadIdx.x;
    const int c = tid & 15;
    const int r = blockIdx.x * 16 + (tid >> 4);
    float v = 0.0f;
    if (r < GG) v = g_pool[r * 16 + c] / fmaxf(g_cnt[r], 1.0f);
    float m = v;
#pragma unroll
    for (int k = 8; k; k >>= 1) m = fmaxf(m, __shfl_xor_sync(0xffffffffu, m, k, 16));
    float e = expf(v - m);
    float s = e;
#pragma unroll
    for (int k = 8; k; k >>= 1) s += __shfl_xor_sync(0xffffffffu, s, k, 16);
    if (r < GG) out[r * 16 + c] = v - m - logf(s);
}

// -----------------------------------------------------------------------------------
extern "C" void kernel_launch(void* const* d_in, const int* in_sizes, int n_in,
                              void* d_out, int out_size) {
    const float* x   = (const float*)d_in[0];
    const float* W1  = (const float*)d_in[1];
    const float* b1  = (const float*)d_in[2];
    const float* W2  = (const float*)d_in[3];
    const float* b2  = (const float*)d_in[4];
    const int* esrc  = (const int*)d_in[5];
    const int* edst  = (const int*)d_in[6];
    const int* batch = (const int*)d_in[7];
    float* out = (float*)d_out;

    // one side stream + two events (proven resource envelope)
    cudaStream_t side;
    cudaEvent_t evP, evB;
    cudaStreamCreateWithFlags(&side, cudaStreamNonBlocking);
    cudaEventCreateWithFlags(&evP, cudaEventDisableTiming);
    cudaEventCreateWithFlags(&evB, cudaEventDisableTiming);

    k_deg<<<(EE / 2 + 255) / 256, 256>>>(edst, W1);        // #1 (main, + W1 cvt)
    k_part<<<NB, 256>>>();                                 // #2 (main)
    cudaEventRecord(evP, 0);                               // dis + W1s + cursor ready
    cudaStreamWaitEvent(side, evP, 0);
    k_gemm1<<<(NN + 63) / 64, 256, 0, side>>>(x);          // #3 (side)
    cudaEventRecord(evB, side);

    k_csr<<<(EE / 2 + 255) / 256, 256>>>(esrc, edst);      // #4 (main) <- ncu

    cudaStreamWaitEvent(0, evB, 0);
    k_agg1<<<(NN / 2 * 32 + 255) / 256, 256>>>(b1);        // #5 (25000 warps)
    k_gemm2<<<(NN * CC) / 256, 256>>>(W2);                 // #6
    k_agg2_pool<<<(NN + 7) / 8, 128>>>(b2, batch);         // #7
    k_out<<<(GG + 15) / 16, 256>>>(out);                   // #8
}